// round 4
// baseline (speedup 1.0000x reference)
#include <cuda_runtime.h>
#include <stdint.h>

#define BSZ  16384
#define KC   8192
#define MAXC 100
#define MINC 20
#define NT   256
#define PER  32
#define CAP  512

// sum over threads with tid' > tid (block exclusive suffix). 2 barriers.
__device__ __forceinline__ int block_suffix_excl(int v, int tid, volatile int* wtmp) {
    int lane = tid & 31, w = tid >> 5;
    int x = v;
    #pragma unroll
    for (int off = 1; off < 32; off <<= 1) {
        int t = __shfl_down_sync(0xFFFFFFFFu, x, off);
        if (lane + off < 32) x += t;
    }
    if (lane == 0) wtmp[w] = x;
    __syncthreads();
    int above = 0;
    #pragma unroll
    for (int j = 0; j < 8; j++) above += (j > w) ? wtmp[j] : 0;
    __syncthreads();
    return above + (x - v);
}

// sum over threads with tid' < tid (block exclusive prefix). 2 barriers. (fallback only)
__device__ __forceinline__ int block_prefix_excl(int v, int tid, volatile int* wtmp) {
    int lane = tid & 31, w = tid >> 5;
    int x = v;
    #pragma unroll
    for (int off = 1; off < 32; off <<= 1) {
        int t = __shfl_up_sync(0xFFFFFFFFu, x, off);
        if (lane >= off) x += t;
    }
    if (lane == 31) wtmp[w] = x;
    __syncthreads();
    int below = 0;
    #pragma unroll
    for (int j = 0; j < 8; j++) below += (j < w) ? wtmp[j] : 0;
    __syncthreads();
    return below + (x - v);
}

__global__ __launch_bounds__(NT, 5) void retention_kernel(
    const float* __restrict__ logits, float* __restrict__ out)
{
    __shared__ uint32_t skeys[KC];      // 32 KB row cache (sortable keys)
    __shared__ int      hist[2048];     // 8 KB
    __shared__ uint32_t ckey[CAP];      // 2 KB candidates (bins >= b)
    __shared__ uint16_t cidx[CAP];      // 1 KB candidate class indices
    __shared__ int      wtmp[8];
    __shared__ int      s_above, sW;
    __shared__ int      s_b, s_need, s_d1, s_need2, s_d0, s_neq;

    const int row  = blockIdx.x;
    const int tid  = threadIdx.x;
    const int lane = tid & 31;
    const int4 z4  = make_int4(0, 0, 0, 0);

    ((int4*)hist)[tid]       = z4;
    ((int4*)hist)[tid + 256] = z4;
    if (tid == 0) sW = 0;
    __syncthreads();

    // ---- Phase 0: load row, 2-instr sortable key, 11-bit histogram ----
    const float4* in4 = (const float4*)(logits + (size_t)row * KC);
    uint4* sk4 = (uint4*)skeys;
    #pragma unroll
    for (int i = 0; i < PER / 4; i++) {
        int v = tid + i * NT;
        float4 f = in4[v];
        uint4 kk; uint32_t u;
        u = __float_as_uint(f.x); kk.x = u ^ (uint32_t)(((int)u >> 31) | (int)0x80000000);
        u = __float_as_uint(f.y); kk.y = u ^ (uint32_t)(((int)u >> 31) | (int)0x80000000);
        u = __float_as_uint(f.z); kk.z = u ^ (uint32_t)(((int)u >> 31) | (int)0x80000000);
        u = __float_as_uint(f.w); kk.w = u ^ (uint32_t)(((int)u >> 31) | (int)0x80000000);
        sk4[v] = kk;
        #pragma unroll
        for (int c = 0; c < 4; c++) {
            uint32_t key = (c == 0) ? kk.x : (c == 1) ? kk.y : (c == 2) ? kk.z : kk.w;
            uint32_t bin = key >> 21;
            unsigned grp = __match_any_sync(0xFFFFFFFFu, bin);   // warp-aggregate
            if (lane == (__ffs(grp) - 1)) atomicAdd(&hist[bin], __popc(grp));
        }
    }
    __syncthreads();

    // ---- Boundary bin + count(logit>=0) from one histogram suffix scan ----
    const int base8 = tid * 8;
    int local = 0;
    #pragma unroll
    for (int j = 0; j < 8; j++) local += hist[base8 + j];
    int above = block_suffix_excl(local, tid, wtmp);
    if (tid == 128) s_above = above + local;   // bins >= 1024 <=> key >= 0x80000000
    __syncthreads();
    const int ktrain = min(max(s_above, MINC), MAXC);
    if (above < ktrain && above + local >= ktrain) {
        int run = above;
        for (int j = 7; j >= 0; j--) {
            int c = hist[base8 + j];
            if (run < ktrain && run + c >= ktrain) { s_b = base8 + j; s_need = ktrain - run; }
            run += c;
        }
    }
    __syncthreads();
    const uint32_t b = (uint32_t)s_b;
    const int need = s_need;

    // ---- Compaction: all keys in bins >= b, with their class indices ----
    #pragma unroll
    for (int i = 0; i < PER / 4; i++) {
        int v = tid + i * NT;                   // conflict-free LDS.128
        uint4 kk = ((const uint4*)skeys)[v];
        #pragma unroll
        for (int c = 0; c < 4; c++) {
            uint32_t key = (c == 0) ? kk.x : (c == 1) ? kk.y : (c == 2) ? kk.z : kk.w;
            bool p = (key >> 21) >= b;
            unsigned m = __ballot_sync(0xFFFFFFFFu, p);
            if (p) {
                int leader = __ffs(m) - 1;
                int prev   = __popc(m & ((1u << lane) - 1));
                int pos;
                if (lane == leader) pos = atomicAdd(&sW, __popc(m));
                pos = __shfl_sync(m, pos, leader) + prev;
                if (pos < CAP) { ckey[pos] = key; cidx[pos] = (uint16_t)(v * 4 + c); }
            }
        }
    }
    __syncthreads();
    const int W = sW;

    float* __restrict__ bs_out  = out;
    float* __restrict__ cls_out = out + (size_t)BSZ * MAXC;
    float* __restrict__ msk_out = out + (size_t)2 * BSZ * MAXC;
    const size_t rbase = (size_t)row * MAXC;

    if (W <= CAP) {
        // ================= FAST PATH: everything over W (~130) candidates =========
        // Sub-pass 1: bits [20:10] of keys in bin b
        ((int4*)hist)[tid] = z4; ((int4*)hist)[tid + 256] = z4;
        __syncthreads();
        for (int i = tid; i < W; i += NT) {
            uint32_t k2 = ckey[i];
            if ((k2 >> 21) == b) atomicAdd(&hist[(k2 >> 10) & 0x7FF], 1);
        }
        __syncthreads();
        {
            int l2 = 0;
            #pragma unroll
            for (int j = 0; j < 8; j++) l2 += hist[base8 + j];
            int ab2 = block_suffix_excl(l2, tid, wtmp);
            if (ab2 < need && ab2 + l2 >= need) {
                int run = ab2;
                for (int j = 7; j >= 0; j--) {
                    int c = hist[base8 + j];
                    if (run < need && run + c >= need) { s_d1 = base8 + j; s_need2 = need - run; }
                    run += c;
                }
            }
        }
        __syncthreads();
        const int need2 = s_need2;
        const uint32_t pref22 = (b << 11) | (uint32_t)s_d1;

        // Sub-pass 2: bits [9:0]
        ((int4*)hist)[tid] = z4;
        __syncthreads();
        for (int i = tid; i < W; i += NT) {
            uint32_t k2 = ckey[i];
            if ((k2 >> 10) == pref22) atomicAdd(&hist[k2 & 0x3FF], 1);
        }
        __syncthreads();
        {
            const int base4 = tid * 4;
            int l2 = 0;
            #pragma unroll
            for (int j = 0; j < 4; j++) l2 += hist[base4 + j];
            int ab2 = block_suffix_excl(l2, tid, wtmp);
            if (ab2 < need2 && ab2 + l2 >= need2) {
                int run = ab2;
                for (int j = 3; j >= 0; j--) {
                    int c = hist[base4 + j];
                    if (run < need2 && run + c >= need2) { s_d0 = base4 + j; s_neq = need2 - run; }
                    run += c;
                }
            }
        }
        __syncthreads();
        const uint32_t T = (pref22 << 10) | (uint32_t)s_d0;
        const int need_eq = s_neq;

        // Emission: rank each selected candidate among candidates (broadcast LDS)
        for (int i = tid; i < W; i += NT) {
            uint32_t ki = ckey[i];
            if (ki < T) continue;
            const int di = cidx[i];
            int gtb = 0, eqb = 0;
            for (int j = 0; j < W; j++) {
                uint32_t kj = ckey[j];
                int lower = (int)cidx[j] < di;
                gtb += (kj > T) & lower;
                eqb += (kj == T) & lower;
            }
            if (ki > T)              cls_out[rbase + gtb + min(eqb, need_eq)] = (float)di;
            else if (eqb < need_eq)  cls_out[rbase + gtb + eqb]               = (float)di;
        }
    } else {
        // ================= FALLBACK (W > CAP, practically never): full scans ======
        ((int4*)hist)[tid] = z4; ((int4*)hist)[tid + 256] = z4;
        __syncthreads();
        for (int i = tid; i < KC; i += NT) {
            uint32_t k2 = skeys[i];
            if ((k2 >> 21) == b) atomicAdd(&hist[(k2 >> 10) & 0x7FF], 1);
        }
        __syncthreads();
        {
            int l2 = 0;
            #pragma unroll
            for (int j = 0; j < 8; j++) l2 += hist[base8 + j];
            int ab2 = block_suffix_excl(l2, tid, wtmp);
            if (ab2 < need && ab2 + l2 >= need) {
                int run = ab2;
                for (int j = 7; j >= 0; j--) {
                    int c = hist[base8 + j];
                    if (run < need && run + c >= need) { s_d1 = base8 + j; s_need2 = need - run; }
                    run += c;
                }
            }
        }
        __syncthreads();
        const int need2 = s_need2;
        const uint32_t pref22 = (b << 11) | (uint32_t)s_d1;

        ((int4*)hist)[tid] = z4;
        __syncthreads();
        for (int i = tid; i < KC; i += NT) {
            uint32_t k2 = skeys[i];
            if ((k2 >> 10) == pref22) atomicAdd(&hist[k2 & 0x3FF], 1);
        }
        __syncthreads();
        {
            const int base4 = tid * 4;
            int l2 = 0;
            #pragma unroll
            for (int j = 0; j < 4; j++) l2 += hist[base4 + j];
            int ab2 = block_suffix_excl(l2, tid, wtmp);
            if (ab2 < need2 && ab2 + l2 >= need2) {
                int run = ab2;
                for (int j = 3; j >= 0; j--) {
                    int c = hist[base4 + j];
                    if (run < need2 && run + c >= need2) { s_d0 = base4 + j; s_neq = need2 - run; }
                    run += c;
                }
            }
        }
        __syncthreads();
        const uint32_t T = (pref22 << 10) | (uint32_t)s_d0;
        const int need_eq = s_neq;

        const int base = tid * PER;
        int gt = 0, eq = 0;
        #pragma unroll 8
        for (int j = 0; j < PER; j++) {
            uint32_t key = skeys[base + ((j + tid) & (PER - 1))];
            gt += (key > T);
            eq += (key == T);
        }
        int excl = block_prefix_excl((gt << 16) | eq, tid, wtmp);
        const int gt_excl = excl >> 16;
        const int eq_excl = excl & 0xFFFF;

        #pragma unroll 1
        for (int j = 0; j < PER; j++) {
            const int lj = (j + tid) & (PER - 1);
            uint32_t key = skeys[base + lj];
            if (key >= T) {
                int lgt = 0, leq = 0;
                for (int m2 = 0; m2 < lj; m2++) {
                    uint32_t k2 = skeys[base + m2];
                    lgt += (k2 > T);
                    leq += (k2 == T);
                }
                int gtb = gt_excl + lgt;
                int eqb = eq_excl + leq;
                if (key > T)             cls_out[rbase + gtb + min(eqb, need_eq)] = (float)(base + lj);
                else if (eqb < need_eq)  cls_out[rbase + gtb + eqb]               = (float)(base + lj);
            }
        }
    }

    // ---- Padding / bs_idx / mask (positions >= ktrain disjoint from selected) ----
    if (tid < MAXC) {
        bs_out[rbase + tid] = (tid < ktrain) ? (float)row : -1.0f;
        if (tid >= ktrain) cls_out[rbase + tid] = -1.0f;
        msk_out[rbase + tid] = (tid < ktrain) ? 1.0f : 0.0f;
    }
}

extern "C" void kernel_launch(void* const* d_in, const int* in_sizes, int n_in,
                              void* d_out, int out_size)
{
    const float* logits = (const float*)d_in[0];
    float* out = (float*)d_out;
    retention_kernel<<<BSZ, NT>>>(logits, out);
}

// round 5
// speedup vs baseline: 1.4829x; 1.4829x over previous
#include <cuda_runtime.h>
#include <stdint.h>

#define BSZ  16384
#define KC   8192
#define MAXC 100
#define MINC 20
#define NT   256
#define PER  32
#define CAP  512

__device__ __forceinline__ uint32_t fkey(uint32_t u) {
    return u ^ (uint32_t)(((int)u >> 31) | (int)0x80000000);   // order-preserving
}

// sum over threads with tid' > tid (block exclusive suffix). 2 barriers.
__device__ __forceinline__ int block_suffix_excl(int v, int tid, volatile int* wtmp) {
    int lane = tid & 31, w = tid >> 5;
    int x = v;
    #pragma unroll
    for (int off = 1; off < 32; off <<= 1) {
        int t = __shfl_down_sync(0xFFFFFFFFu, x, off);
        if (lane + off < 32) x += t;
    }
    if (lane == 0) wtmp[w] = x;
    __syncthreads();
    int above = 0;
    #pragma unroll
    for (int j = 0; j < 8; j++) above += (j > w) ? wtmp[j] : 0;
    __syncthreads();
    return above + (x - v);
}

// sum over threads with tid' < tid (block exclusive prefix). 2 barriers.
__device__ __forceinline__ int block_prefix_excl(int v, int tid, volatile int* wtmp) {
    int lane = tid & 31, w = tid >> 5;
    int x = v;
    #pragma unroll
    for (int off = 1; off < 32; off <<= 1) {
        int t = __shfl_up_sync(0xFFFFFFFFu, x, off);
        if (lane >= off) x += t;
    }
    if (lane == 31) wtmp[w] = x;
    __syncthreads();
    int below = 0;
    #pragma unroll
    for (int j = 0; j < 8; j++) below += (j < w) ? wtmp[j] : 0;
    __syncthreads();
    return below + (x - v);
}

__global__ __launch_bounds__(NT, 6) void retention_kernel(
    const float* __restrict__ logits, float* __restrict__ out)
{
    __shared__ int      hist[2048];     // 8 KB
    __shared__ uint32_t ckey[CAP];      // 2 KB candidate keys (bins >= b)
    __shared__ uint16_t cidx[CAP];      // 1 KB candidate class indices
    __shared__ uint32_t bitmap[NT];     // 1 KB: 8192-bit selection bitmap
    __shared__ int      wtmp[8];
    __shared__ int      s_above, sW;
    __shared__ int      s_b, s_need, s_d1, s_need2, s_d0, s_neq;

    const int row  = blockIdx.x;
    const int tid  = threadIdx.x;
    const int lane = tid & 31;
    const int4 z4  = make_int4(0, 0, 0, 0);

    ((int4*)hist)[tid]       = z4;      // zero 2048 bins
    ((int4*)hist)[tid + 256] = z4;
    bitmap[tid] = 0;
    if (tid == 0) sW = 0;
    __syncthreads();

    // ---- Phase 0: stream row, 11-bit histogram (no smem key cache) ----
    const float4* in4 = (const float4*)(logits + (size_t)row * KC);
    #pragma unroll
    for (int i = 0; i < PER / 4; i++) {
        float4 f = in4[tid + i * NT];
        uint4 kk;
        kk.x = fkey(__float_as_uint(f.x));
        kk.y = fkey(__float_as_uint(f.y));
        kk.z = fkey(__float_as_uint(f.z));
        kk.w = fkey(__float_as_uint(f.w));
        #pragma unroll
        for (int c = 0; c < 4; c++) {
            uint32_t key = (c == 0) ? kk.x : (c == 1) ? kk.y : (c == 2) ? kk.z : kk.w;
            uint32_t bin = key >> 21;
            unsigned grp = __match_any_sync(0xFFFFFFFFu, bin);   // warp-aggregate
            if (lane == (__ffs(grp) - 1)) atomicAdd(&hist[bin], __popc(grp));
        }
    }
    __syncthreads();

    // ---- Boundary bin + count(prob >= 0.5) from one suffix scan ----
    const int base8 = tid * 8;
    int local = 0;
    #pragma unroll
    for (int j = 0; j < 8; j++) local += hist[base8 + j];
    int above = block_suffix_excl(local, tid, wtmp);
    if (tid == 128) s_above = above + local;    // bins >= 1024 <=> logit >= 0
    __syncthreads();
    const int ktrain = min(max(s_above, MINC), MAXC);
    if (above < ktrain && above + local >= ktrain) {
        int run = above;
        for (int j = 7; j >= 0; j--) {
            int c = hist[base8 + j];
            if (run < ktrain && run + c >= ktrain) { s_b = base8 + j; s_need = ktrain - run; }
            run += c;
        }
    }
    __syncthreads();
    const uint32_t b = (uint32_t)s_b;
    const int need = s_need;

    // ---- Compaction: re-read row (L2-hot), collect keys in bins >= b ----
    #pragma unroll
    for (int i = 0; i < PER / 4; i++) {
        int v = tid + i * NT;
        float4 f = in4[v];
        uint4 kk;
        kk.x = fkey(__float_as_uint(f.x));
        kk.y = fkey(__float_as_uint(f.y));
        kk.z = fkey(__float_as_uint(f.z));
        kk.w = fkey(__float_as_uint(f.w));
        #pragma unroll
        for (int c = 0; c < 4; c++) {
            uint32_t key = (c == 0) ? kk.x : (c == 1) ? kk.y : (c == 2) ? kk.z : kk.w;
            bool p = (key >> 21) >= b;
            unsigned m = __ballot_sync(0xFFFFFFFFu, p);
            if (p) {
                int leader = __ffs(m) - 1;
                int prev   = __popc(m & ((1u << lane) - 1));
                int pos;
                if (lane == leader) pos = atomicAdd(&sW, __popc(m));
                pos = __shfl_sync(m, pos, leader) + prev;
                if (pos < CAP) { ckey[pos] = key; cidx[pos] = (uint16_t)(v * 4 + c); }
            }
        }
    }
    __syncthreads();
    const int W = sW;
    uint32_t T;
    int need_eq;

    if (W <= CAP) {
        // ---- FAST PATH: refine T within boundary bin using candidates only ----
        ((int4*)hist)[tid] = z4; ((int4*)hist)[tid + 256] = z4;
        __syncthreads();
        for (int i = tid; i < W; i += NT) {
            uint32_t k2 = ckey[i];
            if ((k2 >> 21) == b) atomicAdd(&hist[(k2 >> 10) & 0x7FF], 1);
        }
        __syncthreads();
        {
            int l2 = 0;
            #pragma unroll
            for (int j = 0; j < 8; j++) l2 += hist[base8 + j];
            int ab2 = block_suffix_excl(l2, tid, wtmp);
            if (ab2 < need && ab2 + l2 >= need) {
                int run = ab2;
                for (int j = 7; j >= 0; j--) {
                    int c = hist[base8 + j];
                    if (run < need && run + c >= need) { s_d1 = base8 + j; s_need2 = need - run; }
                    run += c;
                }
            }
        }
        __syncthreads();
        const int need2 = s_need2;
        const uint32_t pref22 = (b << 11) | (uint32_t)s_d1;

        ((int4*)hist)[tid] = z4;
        __syncthreads();
        for (int i = tid; i < W; i += NT) {
            uint32_t k2 = ckey[i];
            if ((k2 >> 10) == pref22) atomicAdd(&hist[k2 & 0x3FF], 1);
        }
        __syncthreads();
        {
            const int base4 = tid * 4;
            int l2 = 0;
            #pragma unroll
            for (int j = 0; j < 4; j++) l2 += hist[base4 + j];
            int ab2 = block_suffix_excl(l2, tid, wtmp);
            if (ab2 < need2 && ab2 + l2 >= need2) {
                int run = ab2;
                for (int j = 3; j >= 0; j--) {
                    int c = hist[base4 + j];
                    if (run < need2 && run + c >= need2) { s_d0 = base4 + j; s_neq = need2 - run; }
                    run += c;
                }
            }
        }
        __syncthreads();
        T = (pref22 << 10) | (uint32_t)s_d0;
        need_eq = s_neq;

        // ---- Mark bitmap from candidates ----
        for (int i = tid; i < W; i += NT) {
            uint32_t ki = ckey[i];
            int di = cidx[i];
            if (ki > T) {
                atomicOr(&bitmap[di >> 5], 1u << (di & 31));
            } else if (ki == T) {
                int rank = 0;                      // lowest-index equals win (~1 thread)
                for (int j = 0; j < W; j++)
                    rank += (ckey[j] == T) & ((int)cidx[j] < di);
                if (rank < need_eq) atomicOr(&bitmap[di >> 5], 1u << (di & 31));
            }
        }
        __syncthreads();
    } else {
        // ---- FALLBACK (W > CAP, pathological): full global re-scans ----
        ((int4*)hist)[tid] = z4; ((int4*)hist)[tid + 256] = z4;
        __syncthreads();
        const float* in1 = (const float*)in4;
        for (int i = tid; i < KC; i += NT) {
            uint32_t k2 = fkey(__float_as_uint(in1[i]));
            if ((k2 >> 21) == b) atomicAdd(&hist[(k2 >> 10) & 0x7FF], 1);
        }
        __syncthreads();
        {
            int l2 = 0;
            #pragma unroll
            for (int j = 0; j < 8; j++) l2 += hist[base8 + j];
            int ab2 = block_suffix_excl(l2, tid, wtmp);
            if (ab2 < need && ab2 + l2 >= need) {
                int run = ab2;
                for (int j = 7; j >= 0; j--) {
                    int c = hist[base8 + j];
                    if (run < need && run + c >= need) { s_d1 = base8 + j; s_need2 = need - run; }
                    run += c;
                }
            }
        }
        __syncthreads();
        const int need2 = s_need2;
        const uint32_t pref22 = (b << 11) | (uint32_t)s_d1;

        ((int4*)hist)[tid] = z4;
        __syncthreads();
        for (int i = tid; i < KC; i += NT) {
            uint32_t k2 = fkey(__float_as_uint(in1[i]));
            if ((k2 >> 10) == pref22) atomicAdd(&hist[k2 & 0x3FF], 1);
        }
        __syncthreads();
        {
            const int base4 = tid * 4;
            int l2 = 0;
            #pragma unroll
            for (int j = 0; j < 4; j++) l2 += hist[base4 + j];
            int ab2 = block_suffix_excl(l2, tid, wtmp);
            if (ab2 < need2 && ab2 + l2 >= need2) {
                int run = ab2;
                for (int j = 3; j >= 0; j--) {
                    int c = hist[base4 + j];
                    if (run < need2 && run + c >= need2) { s_d0 = base4 + j; s_neq = need2 - run; }
                    run += c;
                }
            }
        }
        __syncthreads();
        T = (pref22 << 10) | (uint32_t)s_d0;
        need_eq = s_neq;

        // mark key>T directly; compact equals for ordered tie-break
        if (tid == 0) sW = 0;
        __syncthreads();
        for (int i = tid; i < KC; i += NT) {
            uint32_t k2 = fkey(__float_as_uint(in1[i]));
            if (k2 > T) atomicOr(&bitmap[i >> 5], 1u << (i & 31));
            else if (k2 == T) {
                int pos = atomicAdd(&sW, 1);
                if (pos < CAP) { ckey[pos] = k2; cidx[pos] = (uint16_t)i; }
            }
        }
        __syncthreads();
        int We = min(sW, CAP);
        for (int i = tid; i < We; i += NT) {
            int di = cidx[i];
            int rank = 0;
            for (int j = 0; j < We; j++) rank += ((int)cidx[j] < di);
            if (rank < need_eq) atomicOr(&bitmap[di >> 5], 1u << (di & 31));
        }
        __syncthreads();
    }

    // ---- Emission: bitmap popcount + block prefix scan + bit walk ----
    uint32_t wbits = bitmap[tid];
    int cnt = __popc(wbits);
    int pos = block_prefix_excl(cnt, tid, wtmp);

    float* __restrict__ bs_out  = out;
    float* __restrict__ cls_out = out + (size_t)BSZ * MAXC;
    float* __restrict__ msk_out = out + (size_t)2 * BSZ * MAXC;
    const size_t rbase = (size_t)row * MAXC;

    while (wbits) {
        int bit = __ffs(wbits) - 1;
        wbits &= wbits - 1;
        cls_out[rbase + pos] = (float)(tid * 32 + bit);
        pos++;
    }

    // ---- Padding / bs_idx / mask ----
    if (tid < MAXC) {
        bs_out[rbase + tid] = (tid < ktrain) ? (float)row : -1.0f;
        if (tid >= ktrain) cls_out[rbase + tid] = -1.0f;
        msk_out[rbase + tid] = (tid < ktrain) ? 1.0f : 0.0f;
    }
}

extern "C" void kernel_launch(void* const* d_in, const int* in_sizes, int n_in,
                              void* d_out, int out_size)
{
    const float* logits = (const float*)d_in[0];
    float* out = (float*)d_out;
    retention_kernel<<<BSZ, NT>>>(logits, out);
}

// round 7
// speedup vs baseline: 1.5597x; 1.0518x over previous
#include <cuda_runtime.h>
#include <stdint.h>

#define BSZ  16384
#define KC   8192
#define MAXC 100
#define MINC 20
#define NT   256
#define PER  32
#define CAP  512

__device__ __forceinline__ uint32_t fkey(uint32_t u) {
    return u ^ (uint32_t)(((int)u >> 31) | (int)0x80000000);   // order-preserving
}

// sum over threads with tid' > tid (block exclusive suffix). 2 barriers.
__device__ __forceinline__ int block_suffix_excl(int v, int tid, volatile int* wtmp) {
    int lane = tid & 31, w = tid >> 5;
    int x = v;
    #pragma unroll
    for (int off = 1; off < 32; off <<= 1) {
        int t = __shfl_down_sync(0xFFFFFFFFu, x, off);
        if (lane + off < 32) x += t;
    }
    if (lane == 0) wtmp[w] = x;
    __syncthreads();
    int above = 0;
    #pragma unroll
    for (int j = 0; j < 8; j++) above += (j > w) ? wtmp[j] : 0;
    __syncthreads();
    return above + (x - v);
}

// sum over threads with tid' < tid (block exclusive prefix). 2 barriers.
__device__ __forceinline__ int block_prefix_excl(int v, int tid, volatile int* wtmp) {
    int lane = tid & 31, w = tid >> 5;
    int x = v;
    #pragma unroll
    for (int off = 1; off < 32; off <<= 1) {
        int t = __shfl_up_sync(0xFFFFFFFFu, x, off);
        if (lane >= off) x += t;
    }
    if (lane == 31) wtmp[w] = x;
    __syncthreads();
    int below = 0;
    #pragma unroll
    for (int j = 0; j < 8; j++) below += (j < w) ? wtmp[j] : 0;
    __syncthreads();
    return below + (x - v);
}

__global__ __launch_bounds__(NT, 5) void retention_kernel(
    const float* __restrict__ logits, float* __restrict__ out)
{
    __shared__ uint32_t skeys[KC];      // 32 KB key cache
    __shared__ int      hist[2048];     // 8 KB
    __shared__ uint32_t ckey[CAP];      // 2 KB candidate keys
    __shared__ uint16_t cidx[CAP];      // 1 KB candidate class indices
    __shared__ uint32_t bitmap[NT];     // 1 KB: 8192-bit selection bitmap
    __shared__ int      wtmp[8];
    __shared__ int      s_above, sW;
    __shared__ int      s_b, s_need, s_d1, s_need2, s_d0, s_neq;

    const int row  = blockIdx.x;
    const int tid  = threadIdx.x;
    const int lane = tid & 31;
    const int4 z4  = make_int4(0, 0, 0, 0);

    ((int4*)hist)[tid]       = z4;
    ((int4*)hist)[tid + 256] = z4;
    bitmap[tid] = 0;
    if (tid == 0) sW = 0;
    __syncthreads();

    // ---- Phase 0: load row once, key-transform, cache in smem, 11-bit hist ----
    const float4* in4 = (const float4*)(logits + (size_t)row * KC);
    uint4* sk4 = (uint4*)skeys;
    #pragma unroll
    for (int i = 0; i < PER / 4; i++) {
        int v = tid + i * NT;
        float4 f = in4[v];
        uint4 kk;
        kk.x = fkey(__float_as_uint(f.x));
        kk.y = fkey(__float_as_uint(f.y));
        kk.z = fkey(__float_as_uint(f.z));
        kk.w = fkey(__float_as_uint(f.w));
        sk4[v] = kk;
        #pragma unroll
        for (int c = 0; c < 4; c++) {
            uint32_t key = (c == 0) ? kk.x : (c == 1) ? kk.y : (c == 2) ? kk.z : kk.w;
            uint32_t bin = key >> 21;
            unsigned grp = __match_any_sync(0xFFFFFFFFu, bin);   // warp-aggregate
            if (lane == (__ffs(grp) - 1)) atomicAdd(&hist[bin], __popc(grp));
        }
    }
    __syncthreads();

    // ---- Boundary bin + count(logit>=0) from one suffix scan ----
    const int base8 = tid * 8;
    int local = 0;
    #pragma unroll
    for (int j = 0; j < 8; j++) local += hist[base8 + j];
    int above = block_suffix_excl(local, tid, wtmp);
    if (tid == 128) s_above = above + local;    // bins >= 1024 <=> logit >= 0
    __syncthreads();
    const int ktrain = min(max(s_above, MINC), MAXC);
    if (above < ktrain && above + local >= ktrain) {
        int run = above;
        for (int j = 7; j >= 0; j--) {
            int c = hist[base8 + j];
            if (run < ktrain && run + c >= ktrain) { s_b = base8 + j; s_need = ktrain - run; }
            run += c;
        }
    }
    __syncthreads();
    const uint32_t b = (uint32_t)s_b;
    const int need = s_need;

    // ---- Compaction from smem: keys in bins >= b (warp-scan aggregated) ----
    #pragma unroll
    for (int i = 0; i < PER / 4; i++) {
        int v = tid + i * NT;                    // conflict-free LDS.128
        uint4 kk = sk4[v];
        int p0 = (kk.x >> 21) >= b;
        int p1 = (kk.y >> 21) >= b;
        int p2 = (kk.z >> 21) >= b;
        int p3 = (kk.w >> 21) >= b;
        int nloc = p0 + p1 + p2 + p3;
        int x = nloc;                            // warp inclusive scan
        #pragma unroll
        for (int off = 1; off < 32; off <<= 1) {
            int t = __shfl_up_sync(0xFFFFFFFFu, x, off);
            if (lane >= off) x += t;
        }
        int base;
        if (lane == 31) base = atomicAdd(&sW, x);
        base = __shfl_sync(0xFFFFFFFFu, base, 31);
        int pos = base + (x - nloc);
        if (nloc) {
            if (p0) { if (pos < CAP) { ckey[pos] = kk.x; cidx[pos] = (uint16_t)(v * 4 + 0); } pos++; }
            if (p1) { if (pos < CAP) { ckey[pos] = kk.y; cidx[pos] = (uint16_t)(v * 4 + 1); } pos++; }
            if (p2) { if (pos < CAP) { ckey[pos] = kk.z; cidx[pos] = (uint16_t)(v * 4 + 2); } pos++; }
            if (p3) { if (pos < CAP) { ckey[pos] = kk.w; cidx[pos] = (uint16_t)(v * 4 + 3); } pos++; }
        }
    }
    __syncthreads();
    const int W = sW;
    uint32_t T;
    int need_eq;

    if (W <= CAP) {
        // ---- FAST PATH: refine T within boundary bin using candidates only ----
        ((int4*)hist)[tid] = z4; ((int4*)hist)[tid + 256] = z4;
        __syncthreads();
        for (int i = tid; i < W; i += NT) {
            uint32_t k2 = ckey[i];
            if ((k2 >> 21) == b) atomicAdd(&hist[(k2 >> 10) & 0x7FF], 1);
        }
        __syncthreads();
        {
            int l2 = 0;
            #pragma unroll
            for (int j = 0; j < 8; j++) l2 += hist[base8 + j];
            int ab2 = block_suffix_excl(l2, tid, wtmp);
            if (ab2 < need && ab2 + l2 >= need) {
                int run = ab2;
                for (int j = 7; j >= 0; j--) {
                    int c = hist[base8 + j];
                    if (run < need && run + c >= need) { s_d1 = base8 + j; s_need2 = need - run; }
                    run += c;
                }
            }
        }
        __syncthreads();
        const int need2 = s_need2;
        const uint32_t pref22 = (b << 11) | (uint32_t)s_d1;

        ((int4*)hist)[tid] = z4;
        __syncthreads();
        for (int i = tid; i < W; i += NT) {
            uint32_t k2 = ckey[i];
            if ((k2 >> 10) == pref22) atomicAdd(&hist[k2 & 0x3FF], 1);
        }
        __syncthreads();
        {
            const int base4 = tid * 4;
            int l2 = 0;
            #pragma unroll
            for (int j = 0; j < 4; j++) l2 += hist[base4 + j];
            int ab2 = block_suffix_excl(l2, tid, wtmp);
            if (ab2 < need2 && ab2 + l2 >= need2) {
                int run = ab2;
                for (int j = 3; j >= 0; j--) {
                    int c = hist[base4 + j];
                    if (run < need2 && run + c >= need2) { s_d0 = base4 + j; s_neq = need2 - run; }
                    run += c;
                }
            }
        }
        __syncthreads();
        T = (pref22 << 10) | (uint32_t)s_d0;
        need_eq = s_neq;

        // ---- Mark bitmap from candidates ----
        for (int i = tid; i < W; i += NT) {
            uint32_t ki = ckey[i];
            int di = cidx[i];
            if (ki > T) {
                atomicOr(&bitmap[di >> 5], 1u << (di & 31));
            } else if (ki == T) {
                int rank = 0;                    // lowest-index equals win (~1 thread)
                for (int j = 0; j < W; j++)
                    rank += (ckey[j] == T) & ((int)cidx[j] < di);
                if (rank < need_eq) atomicOr(&bitmap[di >> 5], 1u << (di & 31));
            }
        }
        __syncthreads();
    } else {
        // ---- FALLBACK (W > CAP, pathological): full smem re-scans ----
        ((int4*)hist)[tid] = z4; ((int4*)hist)[tid + 256] = z4;
        __syncthreads();
        for (int i = tid; i < KC; i += NT) {
            uint32_t k2 = skeys[i];
            if ((k2 >> 21) == b) atomicAdd(&hist[(k2 >> 10) & 0x7FF], 1);
        }
        __syncthreads();
        {
            int l2 = 0;
            #pragma unroll
            for (int j = 0; j < 8; j++) l2 += hist[base8 + j];
            int ab2 = block_suffix_excl(l2, tid, wtmp);
            if (ab2 < need && ab2 + l2 >= need) {
                int run = ab2;
                for (int j = 7; j >= 0; j--) {
                    int c = hist[base8 + j];
                    if (run < need && run + c >= need) { s_d1 = base8 + j; s_need2 = need - run; }
                    run += c;
                }
            }
        }
        __syncthreads();
        const int need2 = s_need2;
        const uint32_t pref22 = (b << 11) | (uint32_t)s_d1;

        ((int4*)hist)[tid] = z4;
        __syncthreads();
        for (int i = tid; i < KC; i += NT) {
            uint32_t k2 = skeys[i];
            if ((k2 >> 10) == pref22) atomicAdd(&hist[k2 & 0x3FF], 1);
        }
        __syncthreads();
        {
            const int base4 = tid * 4;
            int l2 = 0;
            #pragma unroll
            for (int j = 0; j < 4; j++) l2 += hist[base4 + j];
            int ab2 = block_suffix_excl(l2, tid, wtmp);
            if (ab2 < need2 && ab2 + l2 >= need2) {
                int run = ab2;
                for (int j = 3; j >= 0; j--) {
                    int c = hist[base4 + j];
                    if (run < need2 && run + c >= need2) { s_d0 = base4 + j; s_neq = need2 - run; }
                    run += c;
                }
            }
        }
        __syncthreads();
        T = (pref22 << 10) | (uint32_t)s_d0;
        need_eq = s_neq;

        if (tid == 0) sW = 0;
        __syncthreads();
        for (int i = tid; i < KC; i += NT) {
            uint32_t k2 = skeys[i];
            if (k2 > T) atomicOr(&bitmap[i >> 5], 1u << (i & 31));
            else if (k2 == T) {
                int pos = atomicAdd(&sW, 1);
                if (pos < CAP) cidx[pos] = (uint16_t)i;
            }
        }
        __syncthreads();
        int We = min(sW, CAP);
        for (int i = tid; i < We; i += NT) {
            int di = cidx[i];
            int rank = 0;
            for (int j = 0; j < We; j++) rank += ((int)cidx[j] < di);
            if (rank < need_eq) atomicOr(&bitmap[di >> 5], 1u << (di & 31));
        }
        __syncthreads();
    }

    // ---- Emission: bitmap popcount + block prefix scan + bit walk ----
    uint32_t wbits = bitmap[tid];
    int cnt = __popc(wbits);
    int pos = block_prefix_excl(cnt, tid, wtmp);

    float* __restrict__ bs_out  = out;
    float* __restrict__ cls_out = out + (size_t)BSZ * MAXC;
    float* __restrict__ msk_out = out + (size_t)2 * BSZ * MAXC;
    const size_t rbase = (size_t)row * MAXC;

    while (wbits) {
        int bit = __ffs(wbits) - 1;
        wbits &= wbits - 1;
        cls_out[rbase + pos] = (float)(tid * 32 + bit);
        pos++;
    }

    // ---- Padding / bs_idx / mask ----
    if (tid < MAXC) {
        bs_out[rbase + tid] = (tid < ktrain) ? (float)row : -1.0f;
        if (tid >= ktrain) cls_out[rbase + tid] = -1.0f;
        msk_out[rbase + tid] = (tid < ktrain) ? 1.0f : 0.0f;
    }
}

extern "C" void kernel_launch(void* const* d_in, const int* in_sizes, int n_in,
                              void* d_out, int out_size)
{
    const float* logits = (const float*)d_in[0];
    float* out = (float*)d_out;
    retention_kernel<<<BSZ, NT>>>(logits, out);
}

// round 8
// speedup vs baseline: 2.5312x; 1.6229x over previous
#include <cuda_runtime.h>
#include <stdint.h>

#define BSZ  16384
#define KC   8192
#define MAXC 100
#define MINC 20
#define NT   256
#define PER  32
#define CAP  512

__device__ __forceinline__ uint32_t fkey(uint32_t u) {
    return u ^ (uint32_t)(((int)u >> 31) | (int)0x80000000);   // order-preserving
}

// sum over threads with tid' > tid (block exclusive suffix). 2 barriers.
__device__ __forceinline__ int block_suffix_excl(int v, int tid, volatile int* wtmp) {
    int lane = tid & 31, w = tid >> 5;
    int x = v;
    #pragma unroll
    for (int off = 1; off < 32; off <<= 1) {
        int t = __shfl_down_sync(0xFFFFFFFFu, x, off);
        if (lane + off < 32) x += t;
    }
    if (lane == 0) wtmp[w] = x;
    __syncthreads();
    int above = 0;
    #pragma unroll
    for (int j = 0; j < 8; j++) above += (j > w) ? wtmp[j] : 0;
    __syncthreads();
    return above + (x - v);
}

// sum over threads with tid' < tid (block exclusive prefix). 2 barriers.
__device__ __forceinline__ int block_prefix_excl(int v, int tid, volatile int* wtmp) {
    int lane = tid & 31, w = tid >> 5;
    int x = v;
    #pragma unroll
    for (int off = 1; off < 32; off <<= 1) {
        int t = __shfl_up_sync(0xFFFFFFFFu, x, off);
        if (lane >= off) x += t;
    }
    if (lane == 31) wtmp[w] = x;
    __syncthreads();
    int below = 0;
    #pragma unroll
    for (int j = 0; j < 8; j++) below += (j < w) ? wtmp[j] : 0;
    __syncthreads();
    return below + (x - v);
}

__global__ __launch_bounds__(NT, 5) void retention_kernel(
    const float* __restrict__ logits, float* __restrict__ out)
{
    __shared__ uint32_t skeys[KC];      // 32 KB key cache
    __shared__ int      hist[2048];     // 8 KB (reused across passes, read-and-zero)
    __shared__ uint32_t ckey[CAP];      // 2 KB candidate keys
    __shared__ uint16_t cidx[CAP];      // 1 KB candidate class indices
    __shared__ uint32_t bitmap[NT];     // 1 KB selection bitmap
    __shared__ int      wtmp[8];
    __shared__ int      s_above, sW;
    __shared__ int      s_b, s_need, s_d1, s_need2, s_d0, s_neq;

    const int row  = blockIdx.x;
    const int tid  = threadIdx.x;
    const int4 z4  = make_int4(0, 0, 0, 0);

    ((int4*)hist)[2 * tid]     = z4;    // zero 2048 bins (own bins: tid*8..tid*8+7)
    ((int4*)hist)[2 * tid + 1] = z4;
    bitmap[tid] = 0;
    if (tid == 0) sW = 0;
    __syncthreads();

    // ---- Phase 0: load row once, key-transform, cache, plain-atomic 11-bit hist ----
    const float4* in4 = (const float4*)(logits + (size_t)row * KC);
    uint4* sk4 = (uint4*)skeys;
    #pragma unroll
    for (int i = 0; i < PER / 4; i++) {
        int v = tid + i * NT;
        float4 f = in4[v];
        uint4 kk;
        kk.x = fkey(__float_as_uint(f.x));
        kk.y = fkey(__float_as_uint(f.y));
        kk.z = fkey(__float_as_uint(f.z));
        kk.w = fkey(__float_as_uint(f.w));
        sk4[v] = kk;
        atomicAdd(&hist[kk.x >> 21], 1);
        atomicAdd(&hist[kk.y >> 21], 1);
        atomicAdd(&hist[kk.z >> 21], 1);
        atomicAdd(&hist[kk.w >> 21], 1);
    }
    __syncthreads();

    // ---- Scan (read own 8 bins into regs AND zero them), boundary pick ----
    const int base8 = tid * 8;
    int h[8];
    {
        int4 a = ((int4*)hist)[2 * tid];
        int4 bb = ((int4*)hist)[2 * tid + 1];
        h[0] = a.x; h[1] = a.y; h[2] = a.z; h[3] = a.w;
        h[4] = bb.x; h[5] = bb.y; h[6] = bb.z; h[7] = bb.w;
        ((int4*)hist)[2 * tid]     = z4;   // exclusive ownership -> safe, no barrier
        ((int4*)hist)[2 * tid + 1] = z4;
    }
    int local = h[0] + h[1] + h[2] + h[3] + h[4] + h[5] + h[6] + h[7];
    int above = block_suffix_excl(local, tid, wtmp);
    if (tid == 128) s_above = above + local;     // bins >= 1024 <=> logit >= 0
    __syncthreads();
    const int ktrain = min(max(s_above, MINC), MAXC);
    if (above < ktrain && above + local >= ktrain) {
        int run = above;
        for (int j = 7; j >= 0; j--) {
            int c = h[j];
            if (run < ktrain && run + c >= ktrain) { s_b = base8 + j; s_need = ktrain - run; }
            run += c;
        }
    }
    __syncthreads();
    const uint32_t b = (uint32_t)s_b;
    const int need = s_need;

    // ---- Compaction (per-element predicated atomic) + fused bin-b sub-hist ----
    #pragma unroll
    for (int i = 0; i < PER / 4; i++) {
        int v = tid + i * NT;                    // conflict-free LDS.128
        uint4 kk = sk4[v];
        #pragma unroll
        for (int c = 0; c < 4; c++) {
            uint32_t key = (c == 0) ? kk.x : (c == 1) ? kk.y : (c == 2) ? kk.z : kk.w;
            uint32_t bin = key >> 21;
            if (bin >= b) {
                int pos = atomicAdd(&sW, 1);
                if (pos < CAP) { ckey[pos] = key; cidx[pos] = (uint16_t)(v * 4 + c); }
                if (bin == b) atomicAdd(&hist[(key >> 10) & 0x7FF], 1);
            }
        }
    }
    __syncthreads();
    const int W = sW;
    uint32_t T;
    int need_eq;

    if (W <= CAP) {
        // ---- Sub-pass 1 scan (read-and-zero own bins; fill already done above) ----
        {
            int4 a = ((int4*)hist)[2 * tid];
            int4 bb = ((int4*)hist)[2 * tid + 1];
            h[0] = a.x; h[1] = a.y; h[2] = a.z; h[3] = a.w;
            h[4] = bb.x; h[5] = bb.y; h[6] = bb.z; h[7] = bb.w;
            ((int4*)hist)[2 * tid]     = z4;
            ((int4*)hist)[2 * tid + 1] = z4;
        }
        int l2 = h[0] + h[1] + h[2] + h[3] + h[4] + h[5] + h[6] + h[7];
        int ab2 = block_suffix_excl(l2, tid, wtmp);
        if (ab2 < need && ab2 + l2 >= need) {
            int run = ab2;
            for (int j = 7; j >= 0; j--) {
                int c = h[j];
                if (run < need && run + c >= need) { s_d1 = base8 + j; s_need2 = need - run; }
                run += c;
            }
        }
        __syncthreads();
        const int need2 = s_need2;
        const uint32_t pref22 = (b << 11) | (uint32_t)s_d1;

        // ---- Sub-pass 2: fill 1024 bins from candidates (bins pre-zeroed) ----
        for (int i = tid; i < W; i += NT) {
            uint32_t k2 = ckey[i];
            if ((k2 >> 10) == pref22) atomicAdd(&hist[k2 & 0x3FF], 1);
        }
        __syncthreads();
        {
            const int base4 = tid * 4;
            int4 a = ((int4*)hist)[tid];
            int h4[4] = {a.x, a.y, a.z, a.w};
            int l3 = h4[0] + h4[1] + h4[2] + h4[3];
            int ab3 = block_suffix_excl(l3, tid, wtmp);
            if (ab3 < need2 && ab3 + l3 >= need2) {
                int run = ab3;
                for (int j = 3; j >= 0; j--) {
                    int c = h4[j];
                    if (run < need2 && run + c >= need2) { s_d0 = base4 + j; s_neq = need2 - run; }
                    run += c;
                }
            }
        }
        __syncthreads();
        T = (pref22 << 10) | (uint32_t)s_d0;
        need_eq = s_neq;

        // ---- Mark bitmap from candidates ----
        for (int i = tid; i < W; i += NT) {
            uint32_t ki = ckey[i];
            int di = cidx[i];
            if (ki > T) {
                atomicOr(&bitmap[di >> 5], 1u << (di & 31));
            } else if (ki == T) {
                int rank = 0;                    // lowest-index equals win (~1 thread)
                for (int j = 0; j < W; j++)
                    rank += (ckey[j] == T) & ((int)cidx[j] < di);
                if (rank < need_eq) atomicOr(&bitmap[di >> 5], 1u << (di & 31));
            }
        }
        __syncthreads();
    } else {
        // ---- FALLBACK (W > CAP, pathological): full smem re-scans ----
        ((int4*)hist)[2 * tid] = z4; ((int4*)hist)[2 * tid + 1] = z4;
        __syncthreads();
        for (int i = tid; i < KC; i += NT) {
            uint32_t k2 = skeys[i];
            if ((k2 >> 21) == b) atomicAdd(&hist[(k2 >> 10) & 0x7FF], 1);
        }
        __syncthreads();
        {
            int l2 = 0;
            #pragma unroll
            for (int j = 0; j < 8; j++) l2 += hist[base8 + j];
            int ab2 = block_suffix_excl(l2, tid, wtmp);
            if (ab2 < need && ab2 + l2 >= need) {
                int run = ab2;
                for (int j = 7; j >= 0; j--) {
                    int c = hist[base8 + j];
                    if (run < need && run + c >= need) { s_d1 = base8 + j; s_need2 = need - run; }
                    run += c;
                }
            }
        }
        __syncthreads();
        const int need2 = s_need2;
        const uint32_t pref22 = (b << 11) | (uint32_t)s_d1;

        ((int4*)hist)[2 * tid] = z4; ((int4*)hist)[2 * tid + 1] = z4;
        __syncthreads();
        for (int i = tid; i < KC; i += NT) {
            uint32_t k2 = skeys[i];
            if ((k2 >> 10) == pref22) atomicAdd(&hist[k2 & 0x3FF], 1);
        }
        __syncthreads();
        {
            const int base4 = tid * 4;
            int l3 = 0;
            #pragma unroll
            for (int j = 0; j < 4; j++) l3 += hist[base4 + j];
            int ab3 = block_suffix_excl(l3, tid, wtmp);
            if (ab3 < need2 && ab3 + l3 >= need2) {
                int run = ab3;
                for (int j = 3; j >= 0; j--) {
                    int c = hist[base4 + j];
                    if (run < need2 && run + c >= need2) { s_d0 = base4 + j; s_neq = need2 - run; }
                    run += c;
                }
            }
        }
        __syncthreads();
        T = (pref22 << 10) | (uint32_t)s_d0;
        need_eq = s_neq;

        if (tid == 0) sW = 0;
        __syncthreads();
        for (int i = tid; i < KC; i += NT) {
            uint32_t k2 = skeys[i];
            if (k2 > T) atomicOr(&bitmap[i >> 5], 1u << (i & 31));
            else if (k2 == T) {
                int pos = atomicAdd(&sW, 1);
                if (pos < CAP) cidx[pos] = (uint16_t)i;
            }
        }
        __syncthreads();
        int We = min(sW, CAP);
        for (int i = tid; i < We; i += NT) {
            int di = cidx[i];
            int rank = 0;
            for (int j = 0; j < We; j++) rank += ((int)cidx[j] < di);
            if (rank < need_eq) atomicOr(&bitmap[di >> 5], 1u << (di & 31));
        }
        __syncthreads();
    }

    // ---- Emission: bitmap popcount + block prefix scan + bit walk ----
    uint32_t wbits = bitmap[tid];
    int cnt = __popc(wbits);
    int pos = block_prefix_excl(cnt, tid, wtmp);

    float* __restrict__ bs_out  = out;
    float* __restrict__ cls_out = out + (size_t)BSZ * MAXC;
    float* __restrict__ msk_out = out + (size_t)2 * BSZ * MAXC;
    const size_t rbase = (size_t)row * MAXC;

    while (wbits) {
        int bit = __ffs(wbits) - 1;
        wbits &= wbits - 1;
        cls_out[rbase + pos] = (float)(tid * 32 + bit);
        pos++;
    }

    // ---- Padding / bs_idx / mask ----
    if (tid < MAXC) {
        bs_out[rbase + tid] = (tid < ktrain) ? (float)row : -1.0f;
        if (tid >= ktrain) cls_out[rbase + tid] = -1.0f;
        msk_out[rbase + tid] = (tid < ktrain) ? 1.0f : 0.0f;
    }
}

extern "C" void kernel_launch(void* const* d_in, const int* in_sizes, int n_in,
                              void* d_out, int out_size)
{
    const float* logits = (const float*)d_in[0];
    float* out = (float*)d_out;
    retention_kernel<<<BSZ, NT>>>(logits, out);
}